// round 1
// baseline (speedup 1.0000x reference)
#include <cuda_runtime.h>
#include <cuda_bf16.h>
#include <cstdint>

// Problem constants (fixed by setup_inputs)
#define B_   8
#define NCH  32      // centers channels
#define N_   16      // gaussians per (b,k)
#define K_   16
#define H_   128
#define W_   128
#define BK_  (B_ * K_)          // 128
#define HW_  (H_ * W_)          // 16384
#define NPIX ((long long)BK_ * HW_)  // 2097152

// Scratch: separable gaussian factor tables + accumulator
__device__ float g_fx[BK_ * N_ * W_];   // [bk][n][x]
__device__ float g_fy[BK_ * H_ * N_];   // [bk][y][n]
__device__ double g_acc;

// ---------------------------------------------------------------------------
// Kernel A: gather centers/radius, build fx / fy tables, zero accumulator.
// 524288 threads: first half fx, second half fy.
// ---------------------------------------------------------------------------
__global__ void gl_prep(const float* __restrict__ centers,
                        const float* __restrict__ radius,
                        const int*   __restrict__ ind,
                        const float* __restrict__ peak) {
    int i = blockIdx.x * 256 + threadIdx.x;
    if (i == 0) g_acc = 0.0;

    if (i < BK_ * N_ * W_) {
        // fx: layout [bk][n][x]
        int bk = i >> 11;           // / (16*128)
        int n  = (i >> 7) & 15;
        int x  = i & 127;
        int b  = bk >> 4;
        int p  = ind[bk];
        float r   = radius[b * HW_ + p];
        float inv = -0.5f / (r * r);
        float cx  = centers[(b * NCH + 2 * n) * HW_ + p] + peak[bk * 2 + 0];
        float dx  = cx - (float)x;
        g_fx[i] = __expf(inv * dx * dx);
    } else {
        int j  = i - BK_ * N_ * W_;
        // fy: layout [bk][y][n]
        int bk = j >> 11;
        int y  = (j >> 4) & 127;
        int n  = j & 15;
        int b  = bk >> 4;
        int p  = ind[bk];
        float r   = radius[b * HW_ + p];
        float inv = -0.5f / (r * r);
        float cy  = centers[(b * NCH + 2 * n + 1) * HW_ + p] + peak[bk * 2 + 1];
        float dy  = cy - (float)y;
        g_fy[j] = __expf(inv * dy * dy);
    }
}

// ---------------------------------------------------------------------------
// Kernel B: per-pixel g = sum_n fy[n]*fx[n]; sigmoid; masked BCE; reduce.
// grid = BK_*8 blocks (each: one (b,k), 16 rows), 256 threads.
// Thread: fixed x = tid&127, ysub = tid>>7; 8 row-iterations.
// ---------------------------------------------------------------------------
__global__ void gl_main(const float* __restrict__ mask,
                        const float* __restrict__ target) {
    int blk   = blockIdx.x;
    int bk    = blk >> 3;
    int ytile = blk & 7;            // 16 rows per tile
    int tid   = threadIdx.x;
    int x     = tid & 127;
    int ysub  = tid >> 7;           // 0 or 1

    __shared__ float s_fy[16 * 16]; // [row_in_tile][n]
    s_fy[tid] = g_fy[(bk * H_ + ytile * 16) * N_ + tid];

    float fx[16];
#pragma unroll
    for (int n = 0; n < 16; n++)
        fx[n] = g_fx[(bk * N_ + n) * W_ + x];

    float m = mask[bk];
    const float* tg = target + (long long)bk * HW_ + ytile * 16 * W_;

    __syncthreads();

    float acc = 0.0f;
#pragma unroll
    for (int it = 0; it < 8; it++) {
        int yloc = ysub + 2 * it;
        const float4* fy4 = (const float4*)&s_fy[yloc * 16];
        float g0 = 0.f, g1 = 0.f, g2 = 0.f, g3 = 0.f;
#pragma unroll
        for (int q = 0; q < 4; q++) {
            float4 v = fy4[q];
            g0 = fmaf(v.x, fx[4 * q + 0], g0);
            g1 = fmaf(v.y, fx[4 * q + 1], g1);
            g2 = fmaf(v.z, fx[4 * q + 2], g2);
            g3 = fmaf(v.w, fx[4 * q + 3], g3);
        }
        float g = (g0 + g1) + (g2 + g3);

        // sigmoid (precise division to stay close to reference rounding)
        float e = __expf(-g);
        float p = 1.0f / (1.0f + e);

        float xm = p * m;
        float ym = tg[yloc * W_ + x] * m;

        // log(x) and log1p(-x): for x>=0.5, 1-x is exact (Sterbenz), so
        // log(1-x) == log1p(-x). log(0) -> -inf -> clamped to -100.
        float lx  = fmaxf(__logf(xm), -100.0f);
        float l1x = fmaxf(__logf(1.0f - xm), -100.0f);

        acc += ym * lx + (1.0f - ym) * l1x;
    }

    // warp reduce
#pragma unroll
    for (int o = 16; o > 0; o >>= 1)
        acc += __shfl_down_sync(0xffffffffu, acc, o);

    __shared__ float wsum[8];
    if ((tid & 31) == 0) wsum[tid >> 5] = acc;
    __syncthreads();
    if (tid == 0) {
        float s = 0.f;
#pragma unroll
        for (int w = 0; w < 8; w++) s += wsum[w];
        atomicAdd(&g_acc, (double)s);
    }
}

// ---------------------------------------------------------------------------
// Kernel C: finalize loss and broadcast to all output elements.
// ---------------------------------------------------------------------------
__global__ void gl_fin(float* __restrict__ out, int n) {
    float loss = (float)(-g_acc / (double)NPIX);
    for (int i = threadIdx.x; i < n; i += blockDim.x)
        out[i] = loss;
}

extern "C" void kernel_launch(void* const* d_in, const int* in_sizes, int n_in,
                              void* d_out, int out_size) {
    const float* centers = (const float*)d_in[0];
    const float* radius  = (const float*)d_in[1];
    const float* mask    = (const float*)d_in[2];
    const int*   ind     = (const int*)d_in[3];
    const float* target  = (const float*)d_in[4];
    const float* peak    = (const float*)d_in[5];
    float* out = (float*)d_out;

    gl_prep<<<2048, 256>>>(centers, radius, ind, peak);
    gl_main<<<BK_ * 8, 256>>>(mask, target);
    gl_fin<<<1, 256>>>(out, out_size);
}